// round 3
// baseline (speedup 1.0000x reference)
#include <cuda_runtime.h>
#include <cuda_bf16.h>
#include <cstdint>
#include <cstddef>

// ============================================================================
// TTLinear: y = x @ W + bias. W (4096x1024) materialized from TT cores each
// launch; GEMM via bf16 3-term split on mma.sync (HMMA) — tcgen05 is not
// reachable because the harness emits baseline compute_103 PTX.
//   A' [8192, 3072] = [x_hi | x_hi | x_lo]   (bf16, K contiguous)
//   B' [4096, 3072] = [W_hi | W_lo | W_hi]   (bf16, K contiguous)
//   y  = A' B'^T  (fp32 accum) + bias
// ============================================================================

#define BATCH   8192
#define INF     1024
#define OUTF    4096
#define KEXT    3072

__device__ float          g_T01[64 * 8 * 32];               // [m01][r2][n01]
__device__ float          g_T23[8 * 64 * 32];               // [r2][m23][n23]
__device__ __nv_bfloat16  g_A[(size_t)BATCH * KEXT];        // 50.3 MB
__device__ __nv_bfloat16  g_B[(size_t)OUTF  * KEXT];        // 25.2 MB

// ---------------------------------------------------------------------------
// TT preprocessing.  f = n0*256+n1*32+n2*4+n3 ; o = m0*512+m1*64+m2*8+m3
// core0[m0*32+r1*4+n0], core1[r1*512+m1*64+r2*8+n1],
// core2[r2*512+m2*64+r3*8+n2], core3[r3*32+m3*4+n3]
// ---------------------------------------------------------------------------
__global__ void k_tt01(const float* __restrict__ c0, const float* __restrict__ c1) {
    int idx = blockIdx.x * blockDim.x + threadIdx.x;       // 64*8*32 = 16384
    int n01 = idx & 31, r2 = (idx >> 5) & 7, m01 = idx >> 8;
    int m0 = m01 >> 3, m1 = m01 & 7, n0 = n01 >> 3, n1 = n01 & 7;
    float s = 0.f;
#pragma unroll
    for (int r1 = 0; r1 < 8; ++r1)
        s = fmaf(c0[m0 * 32 + r1 * 4 + n0], c1[r1 * 512 + m1 * 64 + r2 * 8 + n1], s);
    g_T01[idx] = s;
}

__global__ void k_tt23(const float* __restrict__ c2, const float* __restrict__ c3) {
    int idx = blockIdx.x * blockDim.x + threadIdx.x;       // 8*64*32 = 16384
    int n23 = idx & 31, m23 = (idx >> 5) & 63, r2 = idx >> 11;
    int m2 = m23 >> 3, m3 = m23 & 7, n2 = n23 >> 2, n3 = n23 & 3;
    float s = 0.f;
#pragma unroll
    for (int r3 = 0; r3 < 8; ++r3)
        s = fmaf(c2[r2 * 512 + m2 * 64 + r3 * 8 + n2], c3[r3 * 32 + m3 * 4 + n3], s);
    g_T23[idx] = s;
}

__global__ void k_buildB() {
    int idx = blockIdx.x * 256 + threadIdx.x;              // OUTF*INF
    int n = idx & 1023, m = idx >> 10;
    int m01 = m >> 6, m23 = m & 63, n01 = n >> 5, n23 = n & 31;
    float s = 0.f;
#pragma unroll
    for (int r2 = 0; r2 < 8; ++r2)
        s = fmaf(g_T01[(m01 * 8 + r2) * 32 + n01], g_T23[(r2 * 64 + m23) * 32 + n23], s);
    __nv_bfloat16 hi = __float2bfloat16(s);
    __nv_bfloat16 lo = __float2bfloat16(s - __bfloat162float(hi));
    size_t base = (size_t)m * KEXT;
    g_B[base + n]        = hi;   // pairs with x_hi
    g_B[base + 1024 + n] = lo;   // pairs with x_hi
    g_B[base + 2048 + n] = hi;   // pairs with x_lo
}

__global__ void k_splitA(const float* __restrict__ x) {
    int idx = blockIdx.x * 256 + threadIdx.x;              // BATCH*INF
    int k = idx & 1023, i = idx >> 10;
    float v = x[idx];
    __nv_bfloat16 hi = __float2bfloat16(v);
    __nv_bfloat16 lo = __float2bfloat16(v - __bfloat162float(hi));
    size_t base = (size_t)i * KEXT;
    g_A[base + k]        = hi;
    g_A[base + 1024 + k] = hi;
    g_A[base + 2048 + k] = lo;
}

// ============================================================================
// GEMM: BM=128, BN=128, BK=32, 256 threads, 4-stage cp.async pipeline,
// mma.sync.m16n8k16 bf16. Warp grid 4x2 -> warp tile 32x64.
// smem row = 64B (32 bf16 of K); XOR swizzle: off ^= ((off>>7)&3)<<4
// (unit' = unit ^ ((row>>1)&3)) -> conflict-free ldmatrix & cp.async.
// ============================================================================

#define BM 128
#define BN 128
#define BK 32
#define STAGES 4
#define NCH (KEXT / BK)              // 96
#define STAGE_BYTES 16384            // A 8KB + B 8KB
#define SW(o) ((o) ^ ((((o) >> 7) & 3u) << 4))

static __device__ __forceinline__ uint32_t s2u(const void* p) {
    uint32_t a;
    asm("{ .reg .u64 t; cvta.to.shared.u64 t, %1; cvt.u32.u64 %0, t; }" : "=r"(a) : "l"(p));
    return a;
}

static __device__ __forceinline__ void ldm_x4(uint32_t* r, uint32_t addr) {
    asm volatile("ldmatrix.sync.aligned.m8n8.x4.shared.b16 {%0,%1,%2,%3}, [%4];"
                 : "=r"(r[0]), "=r"(r[1]), "=r"(r[2]), "=r"(r[3]) : "r"(addr));
}

static __device__ __forceinline__ void mma16816(float* d, const uint32_t* a,
                                                const uint32_t* b) {
    asm volatile(
        "mma.sync.aligned.m16n8k16.row.col.f32.bf16.bf16.f32 "
        "{%0,%1,%2,%3}, {%4,%5,%6,%7}, {%8,%9}, {%0,%1,%2,%3};"
        : "+f"(d[0]), "+f"(d[1]), "+f"(d[2]), "+f"(d[3])
        : "r"(a[0]), "r"(a[1]), "r"(a[2]), "r"(a[3]), "r"(b[0]), "r"(b[1]));
}

__global__ void __launch_bounds__(256, 2)
k_gemm(const float* __restrict__ bias, float* __restrict__ out)
{
    extern __shared__ char dsm[];
    const uint32_t sb = s2u(dsm);
    const int tid  = threadIdx.x;
    const int lane = tid & 31;
    const int w    = tid >> 5;
    const int wm   = w >> 1;           // 0..3 -> m offset *32
    const int wn   = w & 1;            // 0..1 -> n offset *64
    const int m0   = blockIdx.y * BM;
    const int n0   = blockIdx.x * BN;

    // ---- cp.async source/dest (per thread: 2 A units + 2 B units) ----
    const int uid0 = tid * 2;                       // 0..511 step 2
    const int ldrow = uid0 >> 2;                    // 0..127
    const int ldu   = uid0 & 3;                     // 0 or 2
    const uint32_t soff0 = SW((uint32_t)(ldrow * 64 + ldu * 16));
    const uint32_t soff1 = SW((uint32_t)(ldrow * 64 + (ldu + 1) * 16));
    const __nv_bfloat16* gA = g_A + (size_t)(m0 + ldrow) * KEXT + ldu * 8;
    const __nv_bfloat16* gB = g_B + (size_t)(n0 + ldrow) * KEXT + ldu * 8;

    // ---- ldmatrix per-thread addresses ----
    const int quad = lane >> 3, lr = lane & 7;
    const int a_row = wm * 32 + (quad & 1) * 8 + lr;   // + mt*16
    const int a_kb  = ((quad >> 1) & 1) * 16;          // + kk*32
    const int b_row = wn * 64 + ((quad >> 1) & 1) * 8 + lr;  // + g*16
    const int b_kb  = (quad & 1) * 16;                 // + kk*32

    float d[2][8][4];
#pragma unroll
    for (int i = 0; i < 2; ++i)
#pragma unroll
        for (int j = 0; j < 8; ++j)
#pragma unroll
            for (int q = 0; q < 4; ++q) d[i][j][q] = 0.f;

    // ---- prologue: prefetch chunks 0..2 ----
#pragma unroll
    for (int p = 0; p < STAGES - 1; ++p) {
        uint32_t ab = sb + p * STAGE_BYTES;
        asm volatile("cp.async.cg.shared.global [%0], [%1], 16;"
                     :: "r"(ab + soff0), "l"(gA + p * BK) : "memory");
        asm volatile("cp.async.cg.shared.global [%0], [%1], 16;"
                     :: "r"(ab + soff1), "l"(gA + p * BK + 8) : "memory");
        asm volatile("cp.async.cg.shared.global [%0], [%1], 16;"
                     :: "r"(ab + 8192 + soff0), "l"(gB + p * BK) : "memory");
        asm volatile("cp.async.cg.shared.global [%0], [%1], 16;"
                     :: "r"(ab + 8192 + soff1), "l"(gB + p * BK + 8) : "memory");
        asm volatile("cp.async.commit_group;" ::: "memory");
    }

    // ---- mainloop ----
    for (int c = 0; c < NCH; ++c) {
        asm volatile("cp.async.wait_group %0;" :: "n"(STAGES - 2) : "memory");
        __syncthreads();

        int p = c + STAGES - 1;
        if (p < NCH) {
            uint32_t ab = sb + (p & (STAGES - 1)) * STAGE_BYTES;
            asm volatile("cp.async.cg.shared.global [%0], [%1], 16;"
                         :: "r"(ab + soff0), "l"(gA + p * BK) : "memory");
            asm volatile("cp.async.cg.shared.global [%0], [%1], 16;"
                         :: "r"(ab + soff1), "l"(gA + p * BK + 8) : "memory");
            asm volatile("cp.async.cg.shared.global [%0], [%1], 16;"
                         :: "r"(ab + 8192 + soff0), "l"(gB + p * BK) : "memory");
            asm volatile("cp.async.cg.shared.global [%0], [%1], 16;"
                         :: "r"(ab + 8192 + soff1), "l"(gB + p * BK + 8) : "memory");
        }
        asm volatile("cp.async.commit_group;" ::: "memory");

        const uint32_t aB = sb + (c & (STAGES - 1)) * STAGE_BYTES;
        const uint32_t bB = aB + 8192;
#pragma unroll
        for (int kk = 0; kk < 2; ++kk) {
            uint32_t a[2][4], b[4][4];
#pragma unroll
            for (int mt = 0; mt < 2; ++mt) {
                uint32_t off = (uint32_t)((a_row + mt * 16) * 64 + kk * 32 + a_kb);
                ldm_x4(a[mt], aB + SW(off));
            }
#pragma unroll
            for (int g = 0; g < 4; ++g) {
                uint32_t off = (uint32_t)((b_row + g * 16) * 64 + kk * 32 + b_kb);
                ldm_x4(b[g], bB + SW(off));
            }
#pragma unroll
            for (int mt = 0; mt < 2; ++mt)
#pragma unroll
                for (int g = 0; g < 4; ++g) {
                    mma16816(d[mt][g * 2],     a[mt], &b[g][0]);
                    mma16816(d[mt][g * 2 + 1], a[mt], &b[g][2]);
                }
        }
        // next iteration's __syncthreads protects stage reuse
    }

    // ---- epilogue: +bias, write fp32 ----
    const int erow = m0 + wm * 32 + (lane >> 2);
    const int ecol = n0 + wn * 64 + (lane & 3) * 2;
    float2 bvals[8];
#pragma unroll
    for (int nt = 0; nt < 8; ++nt) {
        bvals[nt].x = __ldg(bias + ecol + nt * 8);
        bvals[nt].y = __ldg(bias + ecol + nt * 8 + 1);
    }
#pragma unroll
    for (int mt = 0; mt < 2; ++mt) {
        float* r0 = out + (size_t)(erow + mt * 16) * OUTF + ecol;
        float* r1 = r0 + 8 * OUTF;
#pragma unroll
        for (int nt = 0; nt < 8; ++nt) {
            float2 v0 = { d[mt][nt][0] + bvals[nt].x, d[mt][nt][1] + bvals[nt].y };
            float2 v1 = { d[mt][nt][2] + bvals[nt].x, d[mt][nt][3] + bvals[nt].y };
            *reinterpret_cast<float2*>(r0 + nt * 8) = v0;
            *reinterpret_cast<float2*>(r1 + nt * 8) = v1;
        }
    }
}

// ============================================================================
#define GEMM_SMEM (STAGES * STAGE_BYTES)   // 65536

extern "C" void kernel_launch(void* const* d_in, const int* in_sizes, int n_in,
                              void* d_out, int out_size)
{
    const float* x    = (const float*)d_in[0];
    const float* c0   = (const float*)d_in[1];
    const float* c1   = (const float*)d_in[2];
    const float* c2   = (const float*)d_in[3];
    const float* c3   = (const float*)d_in[4];
    const float* bias = (const float*)d_in[5];
    float* out = (float*)d_out;

    k_tt01<<<64, 256>>>(c0, c1);
    k_tt23<<<64, 256>>>(c2, c3);
    k_buildB<<<(OUTF * INF) / 256, 256>>>();
    k_splitA<<<(BATCH * INF) / 256, 256>>>(x);

    cudaFuncSetAttribute(k_gemm, cudaFuncAttributeMaxDynamicSharedMemorySize, GEMM_SMEM);
    dim3 grid(OUTF / BN, BATCH / BM);   // (32, 64) = 2048 CTAs
    k_gemm<<<grid, 256, GEMM_SMEM>>>(bias, out);
}

// round 4
// speedup vs baseline: 3.9675x; 3.9675x over previous
#include <cuda_runtime.h>
#include <cuda_fp16.h>
#include <cstdint>
#include <cstddef>

// ============================================================================
// TTLinear: y = x @ W + bias. W (4096x1024) materialized from TT cores each
// launch; single fp16 GEMM (K=1024) on mma.sync HMMA with fp32 accumulate.
// fp16 quantization of x and W gives global rel err ~2e-4 << 1e-3 threshold.
// Launch structure: [k_prep, k_buildB, k_gemm] x N  -> ncu -s5 -c1 captures
// launch #6 == k_gemm.
// ============================================================================

#define BATCH   8192
#define INF     1024
#define OUTF    4096
#define KDIM    1024

__device__ float   g_T01[64 * 8 * 32];            // [m01][r2][n01]
__device__ float   g_T23[8 * 64 * 32];            // [r2][m23][n23]
__device__ __half  g_A[(size_t)BATCH * KDIM];     // 16.8 MB
__device__ __half  g_B[(size_t)OUTF  * KDIM];     // 8.4 MB

// ---------------------------------------------------------------------------
// Fused prep: blocks [0,32768) convert x -> fp16 A; [32768,32832) tt01;
// [32832,32896) tt23.  f = n0*256+n1*32+n2*4+n3 ; o = m0*512+m1*64+m2*8+m3
// ---------------------------------------------------------------------------
__global__ void k_prep(const float* __restrict__ x,
                       const float* __restrict__ c0, const float* __restrict__ c1,
                       const float* __restrict__ c2, const float* __restrict__ c3)
{
    int b = blockIdx.x;
    if (b < 32768) {                                    // A convert (8.39M elems)
        int idx = b * 256 + threadIdx.x;
        g_A[idx] = __float2half_rn(x[idx]);
    } else if (b < 32768 + 64) {                        // T01 = c0 x c1 over r1
        int idx = (b - 32768) * 256 + threadIdx.x;      // 16384
        int n01 = idx & 31, r2 = (idx >> 5) & 7, m01 = idx >> 8;
        int m0 = m01 >> 3, m1 = m01 & 7, n0 = n01 >> 3, n1 = n01 & 7;
        float s = 0.f;
#pragma unroll
        for (int r1 = 0; r1 < 8; ++r1)
            s = fmaf(c0[m0 * 32 + r1 * 4 + n0], c1[r1 * 512 + m1 * 64 + r2 * 8 + n1], s);
        g_T01[idx] = s;
    } else {                                            // T23 = c2 x c3 over r3
        int idx = (b - 32832) * 256 + threadIdx.x;      // 16384
        int n23 = idx & 31, m23 = (idx >> 5) & 63, r2 = idx >> 11;
        int m2 = m23 >> 3, m3 = m23 & 7, n2 = n23 >> 2, n3 = n23 & 3;
        float s = 0.f;
#pragma unroll
        for (int r3 = 0; r3 < 8; ++r3)
            s = fmaf(c2[r2 * 512 + m2 * 64 + r3 * 8 + n2], c3[r3 * 32 + m3 * 4 + n3], s);
        g_T23[idx] = s;
    }
}

__global__ void k_buildB() {
    int idx = blockIdx.x * 256 + threadIdx.x;           // OUTF*INF = 4.19M
    int n = idx & 1023, m = idx >> 10;
    int m01 = m >> 6, m23 = m & 63, n01 = n >> 5, n23 = n & 31;
    float s = 0.f;
#pragma unroll
    for (int r2 = 0; r2 < 8; ++r2)
        s = fmaf(g_T01[(m01 * 8 + r2) * 32 + n01], g_T23[(r2 * 64 + m23) * 32 + n23], s);
    g_B[(size_t)m * KDIM + n] = __float2half_rn(s);
}

// ============================================================================
// GEMM: BM=128, BN=128, BK=32, 256 threads, 4-stage cp.async pipeline,
// mma.sync.m16n8k16 f16 (fp32 accum). Warp grid 4x2 -> warp tile 32x64.
// smem row = 64B (32 fp16 of K); XOR swizzle keeps ldmatrix conflict-free.
// ============================================================================

#define BM 128
#define BN 128
#define BK 32
#define STAGES 4
#define NCH (KDIM / BK)              // 32
#define STAGE_BYTES 16384            // A 8KB + B 8KB
#define SW(o) ((o) ^ ((((o) >> 7) & 3u) << 4))

static __device__ __forceinline__ uint32_t s2u(const void* p) {
    uint32_t a;
    asm("{ .reg .u64 t; cvta.to.shared.u64 t, %1; cvt.u32.u64 %0, t; }" : "=r"(a) : "l"(p));
    return a;
}

static __device__ __forceinline__ void ldm_x4(uint32_t* r, uint32_t addr) {
    asm volatile("ldmatrix.sync.aligned.m8n8.x4.shared.b16 {%0,%1,%2,%3}, [%4];"
                 : "=r"(r[0]), "=r"(r[1]), "=r"(r[2]), "=r"(r[3]) : "r"(addr));
}

static __device__ __forceinline__ void mma16816(float* d, const uint32_t* a,
                                                const uint32_t* b) {
    asm volatile(
        "mma.sync.aligned.m16n8k16.row.col.f32.f16.f16.f32 "
        "{%0,%1,%2,%3}, {%4,%5,%6,%7}, {%8,%9}, {%0,%1,%2,%3};"
        : "+f"(d[0]), "+f"(d[1]), "+f"(d[2]), "+f"(d[3])
        : "r"(a[0]), "r"(a[1]), "r"(a[2]), "r"(a[3]), "r"(b[0]), "r"(b[1]));
}

__global__ void __launch_bounds__(256, 2)
k_gemm(const float* __restrict__ bias, float* __restrict__ out)
{
    extern __shared__ char dsm[];
    const uint32_t sb = s2u(dsm);
    const int tid  = threadIdx.x;
    const int lane = tid & 31;
    const int w    = tid >> 5;
    const int wm   = w >> 1;           // 0..3 -> m offset *32
    const int wn   = w & 1;            // 0..1 -> n offset *64
    const int m0   = blockIdx.y * BM;
    const int n0   = blockIdx.x * BN;

    // ---- cp.async source/dest (per thread: 2 A units + 2 B units) ----
    const int uid0 = tid * 2;                       // 0..511 step 2
    const int ldrow = uid0 >> 2;                    // 0..127
    const int ldu   = uid0 & 3;                     // 0 or 2
    const uint32_t soff0 = SW((uint32_t)(ldrow * 64 + ldu * 16));
    const uint32_t soff1 = SW((uint32_t)(ldrow * 64 + (ldu + 1) * 16));
    const __half* gA = g_A + (size_t)(m0 + ldrow) * KDIM + ldu * 8;
    const __half* gB = g_B + (size_t)(n0 + ldrow) * KDIM + ldu * 8;

    // ---- ldmatrix per-thread addresses ----
    const int quad = lane >> 3, lr = lane & 7;
    const int a_row = wm * 32 + (quad & 1) * 8 + lr;          // + mt*16
    const int a_kb  = ((quad >> 1) & 1) * 16;                 // + kk*32
    const int b_row = wn * 64 + ((quad >> 1) & 1) * 8 + lr;   // + g*16
    const int b_kb  = (quad & 1) * 16;                        // + kk*32

    float d[2][8][4];
#pragma unroll
    for (int i = 0; i < 2; ++i)
#pragma unroll
        for (int j = 0; j < 8; ++j)
#pragma unroll
            for (int q = 0; q < 4; ++q) d[i][j][q] = 0.f;

    // ---- prologue: prefetch chunks 0..2 ----
#pragma unroll
    for (int p = 0; p < STAGES - 1; ++p) {
        uint32_t ab = sb + p * STAGE_BYTES;
        asm volatile("cp.async.cg.shared.global [%0], [%1], 16;"
                     :: "r"(ab + soff0), "l"(gA + p * BK) : "memory");
        asm volatile("cp.async.cg.shared.global [%0], [%1], 16;"
                     :: "r"(ab + soff1), "l"(gA + p * BK + 8) : "memory");
        asm volatile("cp.async.cg.shared.global [%0], [%1], 16;"
                     :: "r"(ab + 8192 + soff0), "l"(gB + p * BK) : "memory");
        asm volatile("cp.async.cg.shared.global [%0], [%1], 16;"
                     :: "r"(ab + 8192 + soff1), "l"(gB + p * BK + 8) : "memory");
        asm volatile("cp.async.commit_group;" ::: "memory");
    }

    // ---- mainloop ----
    for (int c = 0; c < NCH; ++c) {
        asm volatile("cp.async.wait_group %0;" :: "n"(STAGES - 2) : "memory");
        __syncthreads();

        int p = c + STAGES - 1;
        if (p < NCH) {
            uint32_t ab = sb + (p & (STAGES - 1)) * STAGE_BYTES;
            asm volatile("cp.async.cg.shared.global [%0], [%1], 16;"
                         :: "r"(ab + soff0), "l"(gA + p * BK) : "memory");
            asm volatile("cp.async.cg.shared.global [%0], [%1], 16;"
                         :: "r"(ab + soff1), "l"(gA + p * BK + 8) : "memory");
            asm volatile("cp.async.cg.shared.global [%0], [%1], 16;"
                         :: "r"(ab + 8192 + soff0), "l"(gB + p * BK) : "memory");
            asm volatile("cp.async.cg.shared.global [%0], [%1], 16;"
                         :: "r"(ab + 8192 + soff1), "l"(gB + p * BK + 8) : "memory");
        }
        asm volatile("cp.async.commit_group;" ::: "memory");

        const uint32_t aB = sb + (c & (STAGES - 1)) * STAGE_BYTES;
        const uint32_t bB = aB + 8192;
#pragma unroll
        for (int kk = 0; kk < 2; ++kk) {
            uint32_t a[2][4], b[4][4];
#pragma unroll
            for (int mt = 0; mt < 2; ++mt) {
                uint32_t off = (uint32_t)((a_row + mt * 16) * 64 + kk * 32 + a_kb);
                ldm_x4(a[mt], aB + SW(off));
            }
#pragma unroll
            for (int g = 0; g < 4; ++g) {
                uint32_t off = (uint32_t)((b_row + g * 16) * 64 + kk * 32 + b_kb);
                ldm_x4(b[g], bB + SW(off));
            }
#pragma unroll
            for (int mt = 0; mt < 2; ++mt)
#pragma unroll
                for (int g = 0; g < 4; ++g) {
                    mma16816(d[mt][g * 2],     a[mt], &b[g][0]);
                    mma16816(d[mt][g * 2 + 1], a[mt], &b[g][2]);
                }
        }
    }

    // ---- epilogue: +bias, write fp32 ----
    const int erow = m0 + wm * 32 + (lane >> 2);
    const int ecol = n0 + wn * 64 + (lane & 3) * 2;
    float2 bvals[8];
#pragma unroll
    for (int nt = 0; nt < 8; ++nt) {
        bvals[nt].x = __ldg(bias + ecol + nt * 8);
        bvals[nt].y = __ldg(bias + ecol + nt * 8 + 1);
    }
#pragma unroll
    for (int mt = 0; mt < 2; ++mt) {
        float* r0 = out + (size_t)(erow + mt * 16) * OUTF + ecol;
        float* r1 = r0 + 8 * OUTF;
#pragma unroll
        for (int nt = 0; nt < 8; ++nt) {
            float2 v0 = { d[mt][nt][0] + bvals[nt].x, d[mt][nt][1] + bvals[nt].y };
            float2 v1 = { d[mt][nt][2] + bvals[nt].x, d[mt][nt][3] + bvals[nt].y };
            *reinterpret_cast<float2*>(r0 + nt * 8) = v0;
            *reinterpret_cast<float2*>(r1 + nt * 8) = v1;
        }
    }
}

// ============================================================================
#define GEMM_SMEM (STAGES * STAGE_BYTES)   // 65536

extern "C" void kernel_launch(void* const* d_in, const int* in_sizes, int n_in,
                              void* d_out, int out_size)
{
    const float* x    = (const float*)d_in[0];
    const float* c0   = (const float*)d_in[1];
    const float* c1   = (const float*)d_in[2];
    const float* c2   = (const float*)d_in[3];
    const float* c3   = (const float*)d_in[4];
    const float* bias = (const float*)d_in[5];
    float* out = (float*)d_out;

    k_prep<<<32768 + 128, 256>>>(x, c0, c1, c2, c3);
    k_buildB<<<(OUTF * INF) / 256, 256>>>();

    cudaFuncSetAttribute(k_gemm, cudaFuncAttributeMaxDynamicSharedMemorySize, GEMM_SMEM);
    dim3 grid(OUTF / BN, BATCH / BM);   // (32, 64) = 2048 CTAs
    k_gemm<<<grid, 256, GEMM_SMEM>>>(bias, out);
}

// round 6
// speedup vs baseline: 4.3849x; 1.1052x over previous
#include <cuda_runtime.h>
#include <cuda_fp16.h>
#include <cstdint>
#include <cstddef>
#include <cstring>

// ============================================================================
// TTLinear: y = x @ W + bias. W (4096x1024) built from TT cores each launch;
// single fp16 GEMM (K=1024) on mma.sync HMMA, fp32 accumulate.
//   R6: 64x64 warp tiles (MMA:LDSM 4:1), 5-stage pipeline, vectorized prep.
// ============================================================================

#define BATCH   8192
#define INF     1024
#define OUTF    4096
#define KDIM    1024

__device__ float   g_T01[64 * 8 * 32];            // [m01][r2][n01]
__device__ float   g_T23[8 * 64 * 32];            // [r2][m23][n23]
__device__ __half  g_A[(size_t)BATCH * KDIM];     // 16.8 MB
__device__ __half  g_B[(size_t)OUTF  * KDIM];     // 8.4 MB

static __device__ __forceinline__ uint32_t h2u(__half2 h) {
    uint32_t u;
    memcpy(&u, &h, 4);
    return u;
}

// ---------------------------------------------------------------------------
// Fused prep: blocks [0,4096) convert x -> fp16 A (8 elems/thread);
// [4096,4160) tt01; [4160,4224) tt23.
// ---------------------------------------------------------------------------
__global__ void k_prep(const float* __restrict__ x,
                       const float* __restrict__ c0, const float* __restrict__ c1,
                       const float* __restrict__ c2, const float* __restrict__ c3)
{
    int b = blockIdx.x;
    if (b < 4096) {                                     // A convert, 8 elems/thread
        int t = b * 256 + threadIdx.x;                  // 1.048M threads
        const float4* x4 = (const float4*)x;
        float4 v0 = x4[t * 2], v1 = x4[t * 2 + 1];
        uint4 o;
        o.x = h2u(__floats2half2_rn(v0.x, v0.y));
        o.y = h2u(__floats2half2_rn(v0.z, v0.w));
        o.z = h2u(__floats2half2_rn(v1.x, v1.y));
        o.w = h2u(__floats2half2_rn(v1.z, v1.w));
        ((uint4*)g_A)[t] = o;
    } else if (b < 4096 + 64) {                         // T01 = c0 x c1 over r1
        int idx = (b - 4096) * 256 + threadIdx.x;       // 16384
        int n01 = idx & 31, r2 = (idx >> 5) & 7, m01 = idx >> 8;
        int m0 = m01 >> 3, m1 = m01 & 7, n0 = n01 >> 3, n1 = n01 & 7;
        float s = 0.f;
#pragma unroll
        for (int r1 = 0; r1 < 8; ++r1)
            s = fmaf(c0[m0 * 32 + r1 * 4 + n0], c1[r1 * 512 + m1 * 64 + r2 * 8 + n1], s);
        g_T01[idx] = s;
    } else {                                            // T23 = c2 x c3 over r3
        int idx = (b - 4160) * 256 + threadIdx.x;       // 16384
        int n23 = idx & 31, m23 = (idx >> 5) & 63, r2 = idx >> 11;
        int m2 = m23 >> 3, m3 = m23 & 7, n2 = n23 >> 2, n3 = n23 & 3;
        float s = 0.f;
#pragma unroll
        for (int r3 = 0; r3 < 8; ++r3)
            s = fmaf(c2[r2 * 512 + m2 * 64 + r3 * 8 + n2], c3[r3 * 32 + m3 * 4 + n3], s);
        g_T23[idx] = s;
    }
}

// B[m][n] = sum_r2 T01[m01][r2][n01] * T23[r2][m23][n23]; 8 outputs/thread.
__global__ void k_buildB() {
    int t = blockIdx.x * 256 + threadIdx.x;             // 524288 threads
    int nb = (t & 127) * 8;                             // n base (8 consecutive)
    int m  = t >> 7;
    int m01 = m >> 6, m23 = m & 63;
    int n01 = nb >> 5, n23b = nb & 31;                  // 8 n's share n01 (8 | 32)
    float s[8] = {0, 0, 0, 0, 0, 0, 0, 0};
#pragma unroll
    for (int r2 = 0; r2 < 8; ++r2) {
        float a = g_T01[(m01 * 8 + r2) * 32 + n01];
        const float4* t23 = (const float4*)&g_T23[(r2 * 64 + m23) * 32 + n23b];
        float4 w0 = t23[0], w1 = t23[1];
        s[0] = fmaf(a, w0.x, s[0]); s[1] = fmaf(a, w0.y, s[1]);
        s[2] = fmaf(a, w0.z, s[2]); s[3] = fmaf(a, w0.w, s[3]);
        s[4] = fmaf(a, w1.x, s[4]); s[5] = fmaf(a, w1.y, s[5]);
        s[6] = fmaf(a, w1.z, s[6]); s[7] = fmaf(a, w1.w, s[7]);
    }
    uint4 o;
    o.x = h2u(__floats2half2_rn(s[0], s[1]));
    o.y = h2u(__floats2half2_rn(s[2], s[3]));
    o.z = h2u(__floats2half2_rn(s[4], s[5]));
    o.w = h2u(__floats2half2_rn(s[6], s[7]));
    ((uint4*)g_B)[((size_t)m * KDIM + nb) / 8] = o;
}

// ============================================================================
// GEMM: BM=256, BN=128, BK=32, 256 threads (8 warps, 4x2), warp tile 64x64,
// 5-stage cp.async pipeline, mma.sync.m16n8k16 f16/f32.
// smem row = 64B; XOR swizzle SW keeps ldmatrix + cp.async conflict-free.
// ============================================================================

#define BM 256
#define BN 128
#define BK 32
#define STAGES 5
#define NCH (KDIM / BK)                       // 32
#define A_SMEM (BM * 64)                      // 16384
#define STAGE_BYTES (A_SMEM + BN * 64)        // 24576
#define SW(o) ((o) ^ ((((o) >> 7) & 3u) << 4))

static __device__ __forceinline__ uint32_t s2u(const void* p) {
    uint32_t a;
    asm("{ .reg .u64 t; cvta.to.shared.u64 t, %1; cvt.u32.u64 %0, t; }" : "=r"(a) : "l"(p));
    return a;
}

static __device__ __forceinline__ void ldm_x4(uint32_t* r, uint32_t addr) {
    asm volatile("ldmatrix.sync.aligned.m8n8.x4.shared.b16 {%0,%1,%2,%3}, [%4];"
                 : "=r"(r[0]), "=r"(r[1]), "=r"(r[2]), "=r"(r[3]) : "r"(addr));
}

static __device__ __forceinline__ void mma16816(float* d, const uint32_t* a,
                                                const uint32_t* b) {
    asm volatile(
        "mma.sync.aligned.m16n8k16.row.col.f32.f16.f16.f32 "
        "{%0,%1,%2,%3}, {%4,%5,%6,%7}, {%8,%9}, {%0,%1,%2,%3};"
        : "+f"(d[0]), "+f"(d[1]), "+f"(d[2]), "+f"(d[3])
        : "r"(a[0]), "r"(a[1]), "r"(a[2]), "r"(a[3]), "r"(b[0]), "r"(b[1]));
}

__global__ void __launch_bounds__(256, 1)
k_gemm(const float* __restrict__ bias, float* __restrict__ out)
{
    extern __shared__ char dsm[];
    const uint32_t sb = s2u(dsm);
    const int tid  = threadIdx.x;
    const int lane = tid & 31;
    const int w    = tid >> 5;
    const int wm   = w >> 1;                  // 0..3 -> m offset *64
    const int wn   = w & 1;                   // 0..1 -> n offset *64
    const int m0   = blockIdx.y * BM;
    const int n0   = blockIdx.x * BN;

    // ---- cp.async mapping: 4 A units + 2 B units per thread ----
    const int ldrow = tid >> 2;               // 0..63 (+j*64)
    const int ldun  = tid & 3;                // 16B unit in 64B row
    uint32_t aoff[4], boff[2];
    const __half *gAp[4], *gBp[2];
#pragma unroll
    for (int j = 0; j < 4; ++j) {
        int r = ldrow + j * 64;
        aoff[j] = SW((uint32_t)(r * 64 + ldun * 16));
        gAp[j]  = g_A + (size_t)(m0 + r) * KDIM + ldun * 8;
    }
#pragma unroll
    for (int j = 0; j < 2; ++j) {
        int r = ldrow + j * 64;
        boff[j] = SW((uint32_t)(r * 64 + ldun * 16));
        gBp[j]  = g_B + (size_t)(n0 + r) * KDIM + ldun * 8;
    }

    // ---- ldmatrix per-thread addressing ----
    const int quad = lane >> 3, lr = lane & 7;
    const int a_row = wm * 64 + (quad & 1) * 8 + lr;          // + mt*16
    const int a_kb  = ((quad >> 1) & 1) * 16;                 // + kk*32
    const int b_row = wn * 64 + ((quad >> 1) & 1) * 8 + lr;   // + g*16
    const int b_kb  = (quad & 1) * 16;                        // + kk*32

    float d[4][8][4];
#pragma unroll
    for (int i = 0; i < 4; ++i)
#pragma unroll
        for (int j = 0; j < 8; ++j)
#pragma unroll
            for (int q = 0; q < 4; ++q) d[i][j][q] = 0.f;

    // ---- prologue: chunks 0..STAGES-2 ----
#pragma unroll
    for (int p = 0; p < STAGES - 1; ++p) {
        uint32_t ab = sb + p * STAGE_BYTES;
#pragma unroll
        for (int j = 0; j < 4; ++j)
            asm volatile("cp.async.cg.shared.global [%0], [%1], 16;"
                         :: "r"(ab + aoff[j]), "l"(gAp[j] + p * BK) : "memory");
#pragma unroll
        for (int j = 0; j < 2; ++j)
            asm volatile("cp.async.cg.shared.global [%0], [%1], 16;"
                         :: "r"(ab + A_SMEM + boff[j]), "l"(gBp[j] + p * BK) : "memory");
        asm volatile("cp.async.commit_group;" ::: "memory");
    }

    // ---- mainloop ----
    int ld = STAGES - 1, rd = 0;
    for (int c = 0; c < NCH; ++c) {
        asm volatile("cp.async.wait_group %0;" :: "n"(STAGES - 2) : "memory");
        __syncthreads();

        int p = c + STAGES - 1;
        if (p < NCH) {
            uint32_t ab = sb + ld * STAGE_BYTES;
#pragma unroll
            for (int j = 0; j < 4; ++j)
                asm volatile("cp.async.cg.shared.global [%0], [%1], 16;"
                             :: "r"(ab + aoff[j]), "l"(gAp[j] + p * BK) : "memory");
#pragma unroll
            for (int j = 0; j < 2; ++j)
                asm volatile("cp.async.cg.shared.global [%0], [%1], 16;"
                             :: "r"(ab + A_SMEM + boff[j]), "l"(gBp[j] + p * BK) : "memory");
        }
        asm volatile("cp.async.commit_group;" ::: "memory");

        const uint32_t aB = sb + rd * STAGE_BYTES;
        const uint32_t bB = aB + A_SMEM;
#pragma unroll
        for (int kk = 0; kk < 2; ++kk) {
            uint32_t a[4][4], bf[4][4];
#pragma unroll
            for (int mt = 0; mt < 4; ++mt) {
                uint32_t off = (uint32_t)((a_row + mt * 16) * 64 + kk * 32 + a_kb);
                ldm_x4(a[mt], aB + SW(off));
            }
#pragma unroll
            for (int g = 0; g < 4; ++g) {
                uint32_t off = (uint32_t)((b_row + g * 16) * 64 + kk * 32 + b_kb);
                ldm_x4(bf[g], bB + SW(off));
            }
#pragma unroll
            for (int mt = 0; mt < 4; ++mt)
#pragma unroll
                for (int g = 0; g < 4; ++g) {
                    mma16816(d[mt][g * 2],     a[mt], &bf[g][0]);
                    mma16816(d[mt][g * 2 + 1], a[mt], &bf[g][2]);
                }
        }
        ld = (ld + 1 == STAGES) ? 0 : ld + 1;
        rd = (rd + 1 == STAGES) ? 0 : rd + 1;
    }

    // ---- epilogue: +bias, write fp32 ----
    const int erow = m0 + wm * 64 + (lane >> 2);
    const int ecol = n0 + wn * 64 + (lane & 3) * 2;
    float2 bvals[8];
#pragma unroll
    for (int nt = 0; nt < 8; ++nt) {
        bvals[nt].x = __ldg(bias + ecol + nt * 8);
        bvals[nt].y = __ldg(bias + ecol + nt * 8 + 1);
    }
#pragma unroll
    for (int mt = 0; mt < 4; ++mt) {
        float* r0 = out + (size_t)(erow + mt * 16) * OUTF + ecol;
        float* r1 = r0 + 8 * OUTF;
#pragma unroll
        for (int nt = 0; nt < 8; ++nt) {
            float2 v0 = { d[mt][nt][0] + bvals[nt].x, d[mt][nt][1] + bvals[nt].y };
            float2 v1 = { d[mt][nt][2] + bvals[nt].x, d[mt][nt][3] + bvals[nt].y };
            *reinterpret_cast<float2*>(r0 + nt * 8) = v0;
            *reinterpret_cast<float2*>(r1 + nt * 8) = v1;
        }
    }
}

// ============================================================================
#define GEMM_SMEM (STAGES * STAGE_BYTES)   // 122880

extern "C" void kernel_launch(void* const* d_in, const int* in_sizes, int n_in,
                              void* d_out, int out_size)
{
    const float* x    = (const float*)d_in[0];
    const float* c0   = (const float*)d_in[1];
    const float* c1   = (const float*)d_in[2];
    const float* c2   = (const float*)d_in[3];
    const float* c3   = (const float*)d_in[4];
    const float* bias = (const float*)d_in[5];
    float* out = (float*)d_out;

    k_prep<<<4096 + 128, 256>>>(x, c0, c1, c2, c3);
    k_buildB<<<2048, 256>>>();

    cudaFuncSetAttribute(k_gemm, cudaFuncAttributeMaxDynamicSharedMemorySize, GEMM_SMEM);
    dim3 grid(OUTF / BN, BATCH / BM);   // (32, 32) = 1024 CTAs
    k_gemm<<<grid, 256, GEMM_SMEM>>>(bias, out);
}

// round 7
// speedup vs baseline: 4.4131x; 1.0064x over previous
#include <cuda_runtime.h>
#include <cuda_fp16.h>
#include <cstdint>
#include <cstddef>
#include <cstring>

// ============================================================================
// TTLinear via two-stage Kronecker-factored GEMM (25.8 GF vs 68.7 GF dense):
//   W[n,m] = sum_r2 T01[m01,r2,n01] * T23[r2,m23,n23],
//     n = n01*32+n23, m = m01*64+m23.
//   Stage1: Z[b, n23, (m01,r2)] = sum_n01 x[b, n01*32+n23] * P[(m01,r2), n01]
//   Stage2: y[b, m01*64+m23]   = sum_{n23,r2} Z[b, n23, (m01,r2)] * Q[(n23,r2), m23]
// P = fp16(T01) [512 x 32], Q[m23][(n23*8+r2)] = fp16(T23), Z fp16 [8192][16384].
// Legacy HMMA (mma.sync) is rate-limited (~330 TF/s) on sm_103a; tcgen05 is
// unreachable (harness emits baseline compute_103 PTX), so we cut FLOPs.
// ============================================================================

#define BATCH   8192
#define OUTF    4096

__device__ __half g_P[512 * 32];                      // [(m01*8+r2)][n01]
__device__ __half g_Q[64 * 256];                      // [m23][(n23*8+r2)]
__device__ __half g_Z[(size_t)BATCH * 16384];         // 268 MB scratch

static __device__ __forceinline__ uint32_t h2u(__half2 h) {
    uint32_t u; memcpy(&u, &h, 4); return u;
}
static __device__ __forceinline__ uint32_t s2u(const void* p) {
    uint32_t a;
    asm("{ .reg .u64 t; cvta.to.shared.u64 t, %1; cvt.u32.u64 %0, t; }" : "=r"(a) : "l"(p));
    return a;
}
static __device__ __forceinline__ void ldm_x4(uint32_t* r, uint32_t addr) {
    asm volatile("ldmatrix.sync.aligned.m8n8.x4.shared.b16 {%0,%1,%2,%3}, [%4];"
                 : "=r"(r[0]), "=r"(r[1]), "=r"(r[2]), "=r"(r[3]) : "r"(addr));
}
static __device__ __forceinline__ void mma16816(float* d, const uint32_t* a,
                                                const uint32_t* b) {
    asm volatile(
        "mma.sync.aligned.m16n8k16.row.col.f32.f16.f16.f32 "
        "{%0,%1,%2,%3}, {%4,%5,%6,%7}, {%8,%9}, {%0,%1,%2,%3};"
        : "+f"(d[0]), "+f"(d[1]), "+f"(d[2]), "+f"(d[3])
        : "r"(a[0]), "r"(a[1]), "r"(a[2]), "r"(a[3]), "r"(b[0]), "r"(b[1]));
}
#define SW(o) ((o) ^ ((((o) >> 7) & 3u) << 4))

// ---------------------------------------------------------------------------
// Prep: blocks [0,64) -> P = fp16(T01); [64,128) -> Q scatter = fp16(T23).
// ---------------------------------------------------------------------------
__global__ void k_prep0(const float* __restrict__ c0, const float* __restrict__ c1,
                        const float* __restrict__ c2, const float* __restrict__ c3)
{
    int b = blockIdx.x;
    if (b < 64) {
        int idx = b * 256 + threadIdx.x;                // [(m01*8+r2)*32 + n01]
        int n01 = idx & 31, r2 = (idx >> 5) & 7, m01 = idx >> 8;
        int m0 = m01 >> 3, m1 = m01 & 7, n0 = n01 >> 3, n1 = n01 & 7;
        float s = 0.f;
#pragma unroll
        for (int r1 = 0; r1 < 8; ++r1)
            s = fmaf(c0[m0 * 32 + r1 * 4 + n0], c1[r1 * 512 + m1 * 64 + r2 * 8 + n1], s);
        g_P[idx] = __float2half_rn(s);
    } else {
        int idx = (b - 64) * 256 + threadIdx.x;         // [r2][m23][n23]
        int n23 = idx & 31, m23 = (idx >> 5) & 63, r2 = idx >> 11;
        int m2 = m23 >> 3, m3 = m23 & 7, n2 = n23 >> 2, n3 = n23 & 3;
        float s = 0.f;
#pragma unroll
        for (int r3 = 0; r3 < 8; ++r3)
            s = fmaf(c2[r2 * 512 + m2 * 64 + r3 * 8 + n2], c3[r3 * 32 + m3 * 4 + n3], s);
        g_Q[m23 * 256 + n23 * 8 + r2] = __float2half_rn(s);
    }
}

// ============================================================================
// Stage 1: tile 256 rows(b,n23) x 128 cols(j=m01*8+r2), K=32. 256 threads,
// warp grid 4x2 (warp tile 64x64). x fp32 loaded + transposed to fp16 smem.
// Grid (4 j-tiles, 1024 b-blocks of 8).
// ============================================================================
__global__ void __launch_bounds__(256)
k_stage1(const float* __restrict__ x)
{
    __shared__ char smem[24576];                        // A 16KB | B(P) 8KB
    const uint32_t sb = s2u(smem);
    const int tid  = threadIdx.x;
    const int lane = tid & 31;
    const int w    = tid >> 5;
    const int wm   = w >> 1;                            // *64 rows
    const int wn   = w & 1;                             // *64 cols
    const int j0   = blockIdx.x * 128;
    const int b0   = blockIdx.y * 8;

    // ---- cp.async P slice: 128 rows x 64B ----
#pragma unroll
    for (int i = 0; i < 2; ++i) {
        int ub = tid + i * 256;
        int row = ub >> 2, u = ub & 3;
        asm volatile("cp.async.cg.shared.global [%0], [%1], 16;"
                     :: "r"(sb + 16384u + SW((uint32_t)(row * 64 + u * 16))),
                        "l"(g_P + (j0 + row) * 32 + u * 8) : "memory");
    }
    asm volatile("cp.async.commit_group;" ::: "memory");

    // ---- x load + transpose: rows (bl,n23), cols n01 (fp16) ----
    {
        const float4* x4 = (const float4*)x;
        int bl = tid >> 5, q0 = tid & 31;
#pragma unroll
        for (int i = 0; i < 8; ++i) {
            int q = q0 + i * 32;                        // 0..255 within row
            float4 f = x4[(size_t)(b0 + bl) * 256 + q];
            int n01 = q >> 3;
            int rbase = bl * 32 + (q & 7) * 4;          // n23 base
            *(__half*)(smem + SW((uint32_t)((rbase + 0) * 64 + n01 * 2))) = __float2half_rn(f.x);
            *(__half*)(smem + SW((uint32_t)((rbase + 1) * 64 + n01 * 2))) = __float2half_rn(f.y);
            *(__half*)(smem + SW((uint32_t)((rbase + 2) * 64 + n01 * 2))) = __float2half_rn(f.z);
            *(__half*)(smem + SW((uint32_t)((rbase + 3) * 64 + n01 * 2))) = __float2half_rn(f.w);
        }
    }
    asm volatile("cp.async.wait_group 0;" ::: "memory");
    __syncthreads();

    // ---- compute: K=32 -> 2 k16 steps ----
    const int quad = lane >> 3, lr = lane & 7;
    const int a_row = wm * 64 + (quad & 1) * 8 + lr;
    const int a_kb  = ((quad >> 1) & 1) * 16;
    const int b_row = wn * 64 + ((quad >> 1) & 1) * 8 + lr;
    const int b_kb  = (quad & 1) * 16;

    float d[4][8][4];
#pragma unroll
    for (int i = 0; i < 4; ++i)
#pragma unroll
        for (int j = 0; j < 8; ++j)
#pragma unroll
            for (int q = 0; q < 4; ++q) d[i][j][q] = 0.f;

#pragma unroll
    for (int kk = 0; kk < 2; ++kk) {
        uint32_t a[4][4], bf[4][4];
#pragma unroll
        for (int mt = 0; mt < 4; ++mt)
            ldm_x4(a[mt], sb + SW((uint32_t)((a_row + mt * 16) * 64 + kk * 32 + a_kb)));
#pragma unroll
        for (int g = 0; g < 4; ++g)
            ldm_x4(bf[g], sb + 16384u + SW((uint32_t)((b_row + g * 16) * 64 + kk * 32 + b_kb)));
#pragma unroll
        for (int mt = 0; mt < 4; ++mt)
#pragma unroll
            for (int g = 0; g < 4; ++g) {
                mma16816(d[mt][g * 2],     a[mt], &bf[g][0]);
                mma16816(d[mt][g * 2 + 1], a[mt], &bf[g][2]);
            }
    }

    // ---- epilogue: fp16 Z, row (b,n23) -> b*16384 + n23*512 + j ----
    const int erow = wm * 64 + (lane >> 2);
    const int ecol = j0 + wn * 64 + (lane & 3) * 2;
#pragma unroll
    for (int mt = 0; mt < 4; ++mt) {
#pragma unroll
        for (int half = 0; half < 2; ++half) {
            int r = erow + mt * 16 + half * 8;          // 0..255
            __half* zp = g_Z + (size_t)(b0 + (r >> 5)) * 16384 + (r & 31) * 512 + ecol;
#pragma unroll
            for (int nt = 0; nt < 8; ++nt) {
                __half2 v = __floats2half2_rn(d[mt][nt][half * 2], d[mt][nt][half * 2 + 1]);
                *(uint32_t*)(zp + nt * 8) = h2u(v);
            }
        }
    }
}

// ============================================================================
// Stage 2: per (m01, b-block): y[128 b x 64 m23] = Z[128 x 256] * Q^T.
// K=256, BK=32, 3-stage cp.async pipeline, 256 threads, warp tile 32x32.
// A K-layout: k = n23*8 + r2; 16B unit u of chunk kc = n23 (kc*4+u).
// ============================================================================
#define S2_STAGE 12288                                  // A 8KB + B 4KB

__global__ void __launch_bounds__(256)
k_stage2(const float* __restrict__ bias, float* __restrict__ out)
{
    __shared__ char smem[3 * S2_STAGE];                 // 36 KB
    const uint32_t sb = s2u(smem);
    const int tid  = threadIdx.x;
    const int lane = tid & 31;
    const int w    = tid >> 5;
    const int wm   = w >> 1;                            // *32 rows (b)
    const int wn   = w & 1;                             // *32 cols (m23)
    const int m01  = blockIdx.x;
    const int b0   = blockIdx.y * 128;

    // A: 2 units/thread (rows r, r+64); B: 1 unit/thread
    const int ar = tid >> 2, au = tid & 3;
    const __half* gA0 = g_Z + (size_t)(b0 + ar) * 16384 + au * 512 + m01 * 8;
    const __half* gA1 = gA0 + (size_t)64 * 16384;
    const uint32_t sa0 = SW((uint32_t)(ar * 64 + au * 16));
    const uint32_t sa1 = SW((uint32_t)((ar + 64) * 64 + au * 16));
    const __half* gB0 = g_Q + (tid >> 2) * 256 + au * 8;
    const uint32_t sb0 = 8192u + SW((uint32_t)((tid >> 2) * 64 + au * 16));

    // ---- prologue: chunks 0,1 ----
#pragma unroll
    for (int p = 0; p < 2; ++p) {
        uint32_t st = sb + p * S2_STAGE;
        asm volatile("cp.async.cg.shared.global [%0], [%1], 16;"
                     :: "r"(st + sa0), "l"(gA0 + p * 2048) : "memory");
        asm volatile("cp.async.cg.shared.global [%0], [%1], 16;"
                     :: "r"(st + sa1), "l"(gA1 + p * 2048) : "memory");
        asm volatile("cp.async.cg.shared.global [%0], [%1], 16;"
                     :: "r"(st + sb0), "l"(gB0 + p * 32) : "memory");
        asm volatile("cp.async.commit_group;" ::: "memory");
    }

    const int quad = lane >> 3, lr = lane & 7;
    const int a_row = wm * 32 + (quad & 1) * 8 + lr;
    const int a_kb  = ((quad >> 1) & 1) * 16;
    const int b_row = wn * 32 + ((quad >> 1) & 1) * 8 + lr;
    const int b_kb  = (quad & 1) * 16;

    float d[2][4][4];
#pragma unroll
    for (int i = 0; i < 2; ++i)
#pragma unroll
        for (int j = 0; j < 4; ++j)
#pragma unroll
            for (int q = 0; q < 4; ++q) d[i][j][q] = 0.f;

    int ld = 2, rd = 0;
#pragma unroll 1
    for (int c = 0; c < 8; ++c) {
        asm volatile("cp.async.wait_group 1;" ::: "memory");
        __syncthreads();

        int p = c + 2;
        if (p < 8) {
            uint32_t st = sb + ld * S2_STAGE;
            asm volatile("cp.async.cg.shared.global [%0], [%1], 16;"
                         :: "r"(st + sa0), "l"(gA0 + p * 2048) : "memory");
            asm volatile("cp.async.cg.shared.global [%0], [%1], 16;"
                         :: "r"(st + sa1), "l"(gA1 + p * 2048) : "memory");
            asm volatile("cp.async.cg.shared.global [%0], [%1], 16;"
                         :: "r"(st + sb0), "l"(gB0 + p * 32) : "memory");
        }
        asm volatile("cp.async.commit_group;" ::: "memory");

        const uint32_t aB = sb + rd * S2_STAGE;
        const uint32_t bB = aB + 8192u;
#pragma unroll
        for (int kk = 0; kk < 2; ++kk) {
            uint32_t a[2][4], bf[2][4];
#pragma unroll
            for (int mt = 0; mt < 2; ++mt)
                ldm_x4(a[mt], aB + SW((uint32_t)((a_row + mt * 16) * 64 + kk * 32 + a_kb)));
#pragma unroll
            for (int g = 0; g < 2; ++g)
                ldm_x4(bf[g], bB + SW((uint32_t)((b_row + g * 16) * 64 + kk * 32 + b_kb)));
#pragma unroll
            for (int mt = 0; mt < 2; ++mt)
#pragma unroll
                for (int g = 0; g < 2; ++g) {
                    mma16816(d[mt][g * 2],     a[mt], &bf[g][0]);
                    mma16816(d[mt][g * 2 + 1], a[mt], &bf[g][2]);
                }
        }
        ld = (ld + 1 == 3) ? 0 : ld + 1;
        rd = (rd + 1 == 3) ? 0 : rd + 1;
    }

    // ---- epilogue: +bias, fp32 ----
    const int erow = b0 + wm * 32 + (lane >> 2);
    const int ecol = m01 * 64 + wn * 32 + (lane & 3) * 2;
    float2 bvals[4];
#pragma unroll
    for (int nt = 0; nt < 4; ++nt) {
        bvals[nt].x = __ldg(bias + ecol + nt * 8);
        bvals[nt].y = __ldg(bias + ecol + nt * 8 + 1);
    }
#pragma unroll
    for (int mt = 0; mt < 2; ++mt) {
        float* r0 = out + (size_t)(erow + mt * 16) * OUTF + ecol;
        float* r1 = r0 + 8 * OUTF;
#pragma unroll
        for (int nt = 0; nt < 4; ++nt) {
            float2 v0 = { d[mt][nt][0] + bvals[nt].x, d[mt][nt][1] + bvals[nt].y };
            float2 v1 = { d[mt][nt][2] + bvals[nt].x, d[mt][nt][3] + bvals[nt].y };
            *reinterpret_cast<float2*>(r0 + nt * 8) = v0;
            *reinterpret_cast<float2*>(r1 + nt * 8) = v1;
        }
    }
}

// ============================================================================
extern "C" void kernel_launch(void* const* d_in, const int* in_sizes, int n_in,
                              void* d_out, int out_size)
{
    const float* x    = (const float*)d_in[0];
    const float* c0   = (const float*)d_in[1];
    const float* c1   = (const float*)d_in[2];
    const float* c2   = (const float*)d_in[3];
    const float* c3   = (const float*)d_in[4];
    const float* bias = (const float*)d_in[5];
    float* out = (float*)d_out;

    k_prep0<<<128, 256>>>(c0, c1, c2, c3);
    k_stage1<<<dim3(4, 1024), 256>>>(x);         // j-tiles fast -> x L2 reuse
    k_stage2<<<dim3(64, 64), 256>>>(bias, out);  // (m01, b-block)
}

// round 8
// speedup vs baseline: 7.0703x; 1.6021x over previous
#include <cuda_runtime.h>
#include <cuda_fp16.h>
#include <cstdint>
#include <cstddef>
#include <cstring>

// ============================================================================
// TTLinear via two-stage Kronecker-factored GEMM (25.8 GF vs 68.7 GF dense):
//   Stage1: Z2[m01][b][n23*8+r2] = sum_n01 x[b, n01*32+n23] * P[(m01*8+r2), n01]
//   Stage2: y[b, m01*64+m23]    = sum_k Z2[m01][b][k] * Q[m23][k],  k=n23*8+r2
// R8: Z plane-major layout -> fully coalesced stage1 writes (128B/warp) and
// contiguous 64B/row/chunk stage2 reads (fixes the 2x sector amplification
// that made R7 DRAM-bound at 219us of stage time).
// ============================================================================

#define BATCH   8192
#define OUTF    4096
#define ZPLANE  (8192 * 256)                          // halves per m01 plane

__device__ __half g_P[512 * 32];                      // [(m01*8+r2)][n01]
__device__ __half g_Q[64 * 256];                      // [m23][(n23*8+r2)]
__device__ __half g_Z[(size_t)64 * ZPLANE];           // 268 MB scratch

static __device__ __forceinline__ uint32_t h2u(__half2 h) {
    uint32_t u; memcpy(&u, &h, 4); return u;
}
static __device__ __forceinline__ uint32_t s2u(const void* p) {
    uint32_t a;
    asm("{ .reg .u64 t; cvta.to.shared.u64 t, %1; cvt.u32.u64 %0, t; }" : "=r"(a) : "l"(p));
    return a;
}
static __device__ __forceinline__ void ldm_x4(uint32_t* r, uint32_t addr) {
    asm volatile("ldmatrix.sync.aligned.m8n8.x4.shared.b16 {%0,%1,%2,%3}, [%4];"
                 : "=r"(r[0]), "=r"(r[1]), "=r"(r[2]), "=r"(r[3]) : "r"(addr));
}
static __device__ __forceinline__ void mma16816(float* d, const uint32_t* a,
                                                const uint32_t* b) {
    asm volatile(
        "mma.sync.aligned.m16n8k16.row.col.f32.f16.f16.f32 "
        "{%0,%1,%2,%3}, {%4,%5,%6,%7}, {%8,%9}, {%0,%1,%2,%3};"
        : "+f"(d[0]), "+f"(d[1]), "+f"(d[2]), "+f"(d[3])
        : "r"(a[0]), "r"(a[1]), "r"(a[2]), "r"(a[3]), "r"(b[0]), "r"(b[1]));
}
#define SW(o) ((o) ^ ((((o) >> 7) & 3u) << 4))

// ---------------------------------------------------------------------------
// Prep: blocks [0,64) -> P = fp16(T01); [64,128) -> Q scatter = fp16(T23).
// ---------------------------------------------------------------------------
__global__ void k_prep0(const float* __restrict__ c0, const float* __restrict__ c1,
                        const float* __restrict__ c2, const float* __restrict__ c3)
{
    int b = blockIdx.x;
    if (b < 64) {
        int idx = b * 256 + threadIdx.x;                // [(m01*8+r2)*32 + n01]
        int n01 = idx & 31, r2 = (idx >> 5) & 7, m01 = idx >> 8;
        int m0 = m01 >> 3, m1 = m01 & 7, n0 = n01 >> 3, n1 = n01 & 7;
        float s = 0.f;
#pragma unroll
        for (int r1 = 0; r1 < 8; ++r1)
            s = fmaf(c0[m0 * 32 + r1 * 4 + n0], c1[r1 * 512 + m1 * 64 + r2 * 8 + n1], s);
        g_P[idx] = __float2half_rn(s);
    } else {
        int idx = (b - 64) * 256 + threadIdx.x;         // [r2][m23][n23]
        int n23 = idx & 31, m23 = (idx >> 5) & 63, r2 = idx >> 11;
        int m2 = m23 >> 3, m3 = m23 & 7, n2 = n23 >> 2, n3 = n23 & 3;
        float s = 0.f;
#pragma unroll
        for (int r3 = 0; r3 < 8; ++r3)
            s = fmaf(c2[r2 * 512 + m2 * 64 + r3 * 8 + n2], c3[r3 * 32 + m3 * 4 + n3], s);
        g_Q[m23 * 256 + n23 * 8 + r2] = __float2half_rn(s);
    }
}

// ============================================================================
// Stage 1: tile 256 rows(b,n23) x 128 cols(j=m01*8+r2), K=32. 256 threads,
// warp grid 4x2 (warp tile 64x64). x fp32 loaded + transposed to fp16 smem.
// Grid (4 j-tiles, 1024 b-blocks of 8). Epilogue: coalesced Z2 plane writes.
// ============================================================================
__global__ void __launch_bounds__(256)
k_stage1(const float* __restrict__ x)
{
    __shared__ char smem[24576];                        // A 16KB | B(P) 8KB
    const uint32_t sb = s2u(smem);
    const int tid  = threadIdx.x;
    const int lane = tid & 31;
    const int w    = tid >> 5;
    const int wm   = w >> 1;                            // *64 rows
    const int wn   = w & 1;                             // *64 cols
    const int j0   = blockIdx.x * 128;
    const int b0   = blockIdx.y * 8;

    // ---- cp.async P slice: 128 rows x 64B ----
#pragma unroll
    for (int i = 0; i < 2; ++i) {
        int ub = tid + i * 256;
        int row = ub >> 2, u = ub & 3;
        asm volatile("cp.async.cg.shared.global [%0], [%1], 16;"
                     :: "r"(sb + 16384u + SW((uint32_t)(row * 64 + u * 16))),
                        "l"(g_P + (j0 + row) * 32 + u * 8) : "memory");
    }
    asm volatile("cp.async.commit_group;" ::: "memory");

    // ---- x load + transpose: rows (bl,n23), cols n01 (fp16) ----
    {
        const float4* x4 = (const float4*)x;
        int bl = tid >> 5, q0 = tid & 31;
#pragma unroll
        for (int i = 0; i < 8; ++i) {
            int q = q0 + i * 32;                        // 0..255 within row
            float4 f = x4[(size_t)(b0 + bl) * 256 + q];
            int n01 = q >> 3;
            int rbase = bl * 32 + (q & 7) * 4;          // n23 base
            *(__half*)(smem + SW((uint32_t)((rbase + 0) * 64 + n01 * 2))) = __float2half_rn(f.x);
            *(__half*)(smem + SW((uint32_t)((rbase + 1) * 64 + n01 * 2))) = __float2half_rn(f.y);
            *(__half*)(smem + SW((uint32_t)((rbase + 2) * 64 + n01 * 2))) = __float2half_rn(f.z);
            *(__half*)(smem + SW((uint32_t)((rbase + 3) * 64 + n01 * 2))) = __float2half_rn(f.w);
        }
    }
    asm volatile("cp.async.wait_group 0;" ::: "memory");
    __syncthreads();

    // ---- compute: K=32 -> 2 k16 steps ----
    const int quad = lane >> 3, lr = lane & 7;
    const int a_row = wm * 64 + (quad & 1) * 8 + lr;
    const int a_kb  = ((quad >> 1) & 1) * 16;
    const int b_row = wn * 64 + ((quad >> 1) & 1) * 8 + lr;
    const int b_kb  = (quad & 1) * 16;

    float d[4][8][4];
#pragma unroll
    for (int i = 0; i < 4; ++i)
#pragma unroll
        for (int j = 0; j < 8; ++j)
#pragma unroll
            for (int q = 0; q < 4; ++q) d[i][j][q] = 0.f;

#pragma unroll
    for (int kk = 0; kk < 2; ++kk) {
        uint32_t a[4][4], bf[4][4];
#pragma unroll
        for (int mt = 0; mt < 4; ++mt)
            ldm_x4(a[mt], sb + SW((uint32_t)((a_row + mt * 16) * 64 + kk * 32 + a_kb)));
#pragma unroll
        for (int g = 0; g < 4; ++g)
            ldm_x4(bf[g], sb + 16384u + SW((uint32_t)((b_row + g * 16) * 64 + kk * 32 + b_kb)));
#pragma unroll
        for (int mt = 0; mt < 4; ++mt)
#pragma unroll
            for (int g = 0; g < 4; ++g) {
                mma16816(d[mt][g * 2],     a[mt], &bf[g][0]);
                mma16816(d[mt][g * 2 + 1], a[mt], &bf[g][2]);
            }
    }

    // ---- epilogue: Z2[m01][b][n23*8+r2]; warp stores 128B contiguous runs ----
    const int m01b = blockIdx.x * 16 + wn * 8;          // + nt
    const int r2p  = (lane & 3) * 2;                    // r2 pair
#pragma unroll
    for (int mt = 0; mt < 4; ++mt) {
#pragma unroll
        for (int half = 0; half < 2; ++half) {
            int r = wm * 64 + mt * 16 + half * 8 + (lane >> 2);   // 0..255
            size_t boff = (size_t)(b0 + (r >> 5)) * 256 + (r & 31) * 8 + r2p;
#pragma unroll
            for (int nt = 0; nt < 8; ++nt) {
                __half2 v = __floats2half2_rn(d[mt][nt][half * 2], d[mt][nt][half * 2 + 1]);
                *(uint32_t*)(g_Z + (size_t)(m01b + nt) * ZPLANE + boff) = h2u(v);
            }
        }
    }
}

// ============================================================================
// Stage 2: CTA (m01, b-block 256): y[256 x 64] = Z2_plane[256 x 256] * Q^T.
// 256 threads, 8 warps (4x2), warp tile 64x32, K=256, BK=32, 3-stage pipeline.
// A chunk rows are contiguous 64B slices of 512B Z2 rows -> full sectors.
// ============================================================================
#define S2_STAGE 20480                                  // A 16KB + B(Q) 4KB

__global__ void __launch_bounds__(256)
k_stage2(const float* __restrict__ bias, float* __restrict__ out)
{
    extern __shared__ char smem[];                      // 3 * 20480 = 60KB
    const uint32_t sb = s2u(smem);
    const int tid  = threadIdx.x;
    const int lane = tid & 31;
    const int w    = tid >> 5;
    const int wm   = w >> 1;                            // *64 rows (b)
    const int wn   = w & 1;                             // *32 cols (m23)
    const int m01  = blockIdx.x;
    const int b0   = blockIdx.y * 256;

    const __half* plane = g_Z + (size_t)m01 * ZPLANE;

    // cp.async: A 4 units/thread (rows ar+i*64), B 1 unit/thread
    const int ar = tid >> 2, au = tid & 3;
    const __half* gA = plane + (size_t)(b0 + ar) * 256 + au * 8;
    const __half* gB = g_Q + ar * 256 + au * 8;
    uint32_t saA[4];
#pragma unroll
    for (int i = 0; i < 4; ++i)
        saA[i] = SW((uint32_t)((ar + i * 64) * 64 + au * 16));
    const uint32_t saB = 16384u + SW((uint32_t)(ar * 64 + au * 16));

    // ---- prologue: chunks 0,1 ----
#pragma unroll
    for (int p = 0; p < 2; ++p) {
        uint32_t st = sb + p * S2_STAGE;
#pragma unroll
        for (int i = 0; i < 4; ++i)
            asm volatile("cp.async.cg.shared.global [%0], [%1], 16;"
                         :: "r"(st + saA[i]), "l"(gA + (size_t)i * 64 * 256 + p * 32) : "memory");
        asm volatile("cp.async.cg.shared.global [%0], [%1], 16;"
                     :: "r"(st + saB), "l"(gB + p * 32) : "memory");
        asm volatile("cp.async.commit_group;" ::: "memory");
    }

    const int quad = lane >> 3, lr = lane & 7;
    const int a_row = wm * 64 + (quad & 1) * 8 + lr;
    const int a_kb  = ((quad >> 1) & 1) * 16;
    const int b_row = wn * 32 + ((quad >> 1) & 1) * 8 + lr;
    const int b_kb  = (quad & 1) * 16;

    float d[4][4][4];
#pragma unroll
    for (int i = 0; i < 4; ++i)
#pragma unroll
        for (int j = 0; j < 4; ++j)
#pragma unroll
            for (int q = 0; q < 4; ++q) d[i][j][q] = 0.f;

    int ld = 2, rd = 0;
#pragma unroll 1
    for (int c = 0; c < 8; ++c) {
        asm volatile("cp.async.wait_group 1;" ::: "memory");
        __syncthreads();

        int p = c + 2;
        if (p < 8) {
            uint32_t st = sb + ld * S2_STAGE;
#pragma unroll
            for (int i = 0; i < 4; ++i)
                asm volatile("cp.async.cg.shared.global [%0], [%1], 16;"
                             :: "r"(st + saA[i]), "l"(gA + (size_t)i * 64 * 256 + p * 32) : "memory");
            asm volatile("cp.async.cg.shared.global [%0], [%1], 16;"
                         :: "r"(st + saB), "l"(gB + p * 32) : "memory");
        }
        asm volatile("cp.async.commit_group;" ::: "memory");

        const uint32_t aB = sb + rd * S2_STAGE;
        const uint32_t bB = aB + 16384u;
#pragma unroll
        for (int kk = 0; kk < 2; ++kk) {
            uint32_t a[4][4], bf[2][4];
#pragma unroll
            for (int mt = 0; mt < 4; ++mt)
                ldm_x4(a[mt], aB + SW((uint32_t)((a_row + mt * 16) * 64 + kk * 32 + a_kb)));
#pragma unroll
            for (int g = 0; g < 2; ++g)
                ldm_x4(bf[g], bB + SW((uint32_t)((b_row + g * 16) * 64 + kk * 32 + b_kb)));
#pragma unroll
            for (int mt = 0; mt < 4; ++mt)
#pragma unroll
                for (int g = 0; g < 2; ++g) {
                    mma16816(d[mt][g * 2],     a[mt], &bf[g][0]);
                    mma16816(d[mt][g * 2 + 1], a[mt], &bf[g][2]);
                }
        }
        ld = (ld + 1 == 3) ? 0 : ld + 1;
        rd = (rd + 1 == 3) ? 0 : rd + 1;
    }

    // ---- epilogue: +bias, fp32 ----
    const int erow = b0 + wm * 64 + (lane >> 2);
    const int ecol = m01 * 64 + wn * 32 + (lane & 3) * 2;
    float2 bvals[4];
#pragma unroll
    for (int nt = 0; nt < 4; ++nt) {
        bvals[nt].x = __ldg(bias + ecol + nt * 8);
        bvals[nt].y = __ldg(bias + ecol + nt * 8 + 1);
    }
#pragma unroll
    for (int mt = 0; mt < 4; ++mt) {
        float* r0 = out + (size_t)(erow + mt * 16) * OUTF + ecol;
        float* r1 = r0 + 8 * OUTF;
#pragma unroll
        for (int nt = 0; nt < 4; ++nt) {
            float2 v0 = { d[mt][nt][0] + bvals[nt].x, d[mt][nt][1] + bvals[nt].y };
            float2 v1 = { d[mt][nt][2] + bvals[nt].x, d[mt][nt][3] + bvals[nt].y };
            *reinterpret_cast<float2*>(r0 + nt * 8) = v0;
            *reinterpret_cast<float2*>(r1 + nt * 8) = v1;
        }
    }
}

// ============================================================================
extern "C" void kernel_launch(void* const* d_in, const int* in_sizes, int n_in,
                              void* d_out, int out_size)
{
    const float* x    = (const float*)d_in[0];
    const float* c0   = (const float*)d_in[1];
    const float* c1   = (const float*)d_in[2];
    const float* c2   = (const float*)d_in[3];
    const float* c3   = (const float*)d_in[4];
    const float* bias = (const float*)d_in[5];
    float* out = (float*)d_out;

    k_prep0<<<128, 256>>>(c0, c1, c2, c3);
    k_stage1<<<dim3(4, 1024), 256>>>(x);
    cudaFuncSetAttribute(k_stage2, cudaFuncAttributeMaxDynamicSharedMemorySize,
                         3 * S2_STAGE);
    k_stage2<<<dim3(64, 32), 256, 3 * S2_STAGE>>>(bias, out);
}